// round 1
// baseline (speedup 1.0000x reference)
#include <cuda_runtime.h>
#include <math.h>

#define BB 64
#define SS 512
#define DD 768
#define HH 4
#define DHH 192
#define PP 8
#define NPER 9
#define NN 576        // BB*NPER
#define E0 4096
#define NE 8768       // 2*E0 + NN (symmetrized + self loops)

// -------- device scratch (no allocs allowed) --------
__device__ float g_x[NN * DD];     // node features (layer input)
__device__ float g_h[NN * DD];     // h = x @ W
__device__ float g_acc[NN * DD];   // aggregated messages
__device__ float g_as[NN * HH];
__device__ float g_ad[NN * HH];
__device__ float g_e[NE * HH];     // edge logits -> exp values
__device__ float g_m[NN * HH];
__device__ float g_den[NN * HH];

__device__ __forceinline__ void edge_sd(int e, const int* __restrict__ ei, int& s, int& d) {
    if (e < E0)            { s = ei[e];           d = ei[E0 + e]; }
    else if (e < 2 * E0)   { s = ei[E0 + e - E0]; d = ei[e - E0]; }
    else                   { s = e - 2 * E0;      d = e - 2 * E0; }
}

__device__ __forceinline__ void atomicMaxFloat(float* addr, float v) {
    if (v >= 0.0f) atomicMax((int*)addr, __float_as_int(v));
    else           atomicMin((unsigned int*)addr, __float_as_uint(v));
}

// -------- 1. build GNN nodes --------
__global__ void build_nodes(const int* __restrict__ src,
                            const int* __restrict__ sstart,
                            const int* __restrict__ send,
                            const float* __restrict__ wt) {
    int node = blockIdx.x;
    int b = node / NPER, p = node % NPER;
    for (int d = threadIdx.x; d < DD; d += blockDim.x) {
        float v = 0.0f;
        if (p == 0) {
            v = wt[(size_t)src[b * SS] * DD + d];
        } else {
            int st = sstart[b * PP + (p - 1)];
            int en = send[b * PP + (p - 1)];
            for (int s = st; s <= en; s++)
                v += wt[(size_t)src[b * SS + s] * DD + d];
        }
        g_x[node * DD + d] = v;
    }
}

// -------- 2. GEMM: g_h = g_x @ W  (576x768x768, fp32) --------
__global__ void gemm_xw(const float* __restrict__ Wl) {
    __shared__ float As[16][68];   // [k][m], padded to dodge store conflicts
    __shared__ float Bs[16][64];   // [k][n]
    int bm = blockIdx.y * 64, bn = blockIdx.x * 64;
    int tid = threadIdx.x;
    int tr = tid / 16, tc = tid % 16;
    float acc[4][4];
#pragma unroll
    for (int i = 0; i < 4; i++)
#pragma unroll
        for (int j = 0; j < 4; j++) acc[i][j] = 0.0f;

    for (int k0 = 0; k0 < DD; k0 += 16) {
        // load A tile 64x16 (coalesced along k)
        for (int i = tid; i < 64 * 16; i += 256) {
            int m = i / 16, k = i % 16;
            As[k][m] = g_x[(bm + m) * DD + k0 + k];
        }
        // load B tile 16x64 (coalesced along n)
        for (int i = tid; i < 16 * 64; i += 256) {
            int k = i / 64, n = i % 64;
            Bs[k][n] = Wl[(size_t)(k0 + k) * DD + bn + n];
        }
        __syncthreads();
#pragma unroll
        for (int k = 0; k < 16; k++) {
            float a[4], bv[4];
#pragma unroll
            for (int i = 0; i < 4; i++) a[i]  = As[k][tr * 4 + i];
#pragma unroll
            for (int j = 0; j < 4; j++) bv[j] = Bs[k][tc * 4 + j];
#pragma unroll
            for (int i = 0; i < 4; i++)
#pragma unroll
                for (int j = 0; j < 4; j++) acc[i][j] += a[i] * bv[j];
        }
        __syncthreads();
    }
#pragma unroll
    for (int i = 0; i < 4; i++) {
        int gm = bm + tr * 4 + i;
#pragma unroll
        for (int j = 0; j < 4; j++)
            g_h[gm * DD + bn + tc * 4 + j] = acc[i][j];
    }
}

// -------- 3. attention logit coefficients per (node, head) --------
__global__ void alphas_kernel(const float* __restrict__ a_s,
                              const float* __restrict__ a_d) {
    int node = blockIdx.x;
    int h = threadIdx.x / 32, lane = threadIdx.x % 32;
    float ss = 0.0f, sd = 0.0f;
    for (int i = lane; i < DHH; i += 32) {
        float hv = g_h[node * DD + h * DHH + i];
        ss += hv * a_s[h * DHH + i];
        sd += hv * a_d[h * DHH + i];
    }
#pragma unroll
    for (int o = 16; o; o >>= 1) {
        ss += __shfl_xor_sync(0xffffffffu, ss, o);
        sd += __shfl_xor_sync(0xffffffffu, sd, o);
    }
    if (lane == 0) { g_as[node * HH + h] = ss; g_ad[node * HH + h] = sd; }
}

// -------- 4. init accumulators --------
__global__ void init_kernel() {
    int idx = blockIdx.x * blockDim.x + threadIdx.x;
    if (idx < NN * DD) g_acc[idx] = 0.0f;
    if (idx < NN * HH) { g_m[idx] = -3.0e38f; g_den[idx] = 0.0f; }
}

// -------- 5. edge logits + segment max --------
__global__ void edge_logit(const int* __restrict__ ei) {
    int idx = blockIdx.x * blockDim.x + threadIdx.x;
    if (idx >= NE * HH) return;
    int e = idx / HH, h = idx % HH;
    int s, d; edge_sd(e, ei, s, d);
    float v = g_as[s * HH + h] + g_ad[d * HH + h];
    v = (v > 0.0f) ? v : 0.2f * v;           // leaky_relu(0.2)
    g_e[idx] = v;
    atomicMaxFloat(&g_m[d * HH + h], v);
}

// -------- 6. exp + segment sum --------
__global__ void edge_exp(const int* __restrict__ ei) {
    int idx = blockIdx.x * blockDim.x + threadIdx.x;
    if (idx >= NE * HH) return;
    int e = idx / HH, h = idx % HH;
    int s, d; edge_sd(e, ei, s, d);
    float ex = expf(g_e[idx] - g_m[d * HH + h]);
    g_e[idx] = ex;
    atomicAdd(&g_den[d * HH + h], ex);
}

// -------- 7. message aggregation (warp per edge) --------
__global__ void aggregate(const int* __restrict__ ei) {
    int e = blockIdx.x * (blockDim.x / 32) + threadIdx.x / 32;
    if (e >= NE) return;
    int lane = threadIdx.x & 31;
    int s, d; edge_sd(e, ei, s, d);
#pragma unroll
    for (int i = 0; i < 24; i++) {
        int j = lane + i * 32;
        int h = j / DHH;
        float att = g_e[e * HH + h] / g_den[d * HH + h];
        atomicAdd(&g_acc[d * DD + j], att * g_h[s * DD + j]);
    }
}

// -------- 8. bias + exact GELU --------
__global__ void bias_gelu(const float* __restrict__ bl) {
    int idx = blockIdx.x * blockDim.x + threadIdx.x;
    if (idx >= NN * DD) return;
    float v = g_acc[idx] + bl[idx % DD];
    v = 0.5f * v * (1.0f + erff(v * 0.70710678118654752f));
    g_x[idx] = v;
}

// -------- 9. final embedding sum + LayerNorm (warp per row) --------
__global__ void final_ln(const int* __restrict__ src, const int* __restrict__ seg,
                         const int* __restrict__ typ, const int* __restrict__ pos,
                         const float* __restrict__ wt, const float* __restrict__ pt,
                         const float* __restrict__ st, const float* __restrict__ tt,
                         const float* __restrict__ gamma, const float* __restrict__ beta,
                         float* __restrict__ out) {
    int row = blockIdx.x * 8 + threadIdx.x / 32;   // BB*SS rows total
    int lane = threadIdx.x & 31;
    int b = row / SS, s = row % SS;
    const float* wrow = (s == 0) ? &g_x[(b * NPER) * DD]
                                 : &wt[(size_t)src[row] * DD];
    const float* prow = &pt[(size_t)pos[row] * DD];
    const float* srow = &st[(size_t)seg[row] * DD];
    const float* trow = &tt[(size_t)typ[row] * DD];
    float v[24];
    float sum = 0.0f, sq = 0.0f;
#pragma unroll
    for (int i = 0; i < 24; i++) {
        int d = lane + i * 32;
        float e = wrow[d] + prow[d] + srow[d] + trow[d];
        v[i] = e; sum += e; sq += e * e;
    }
#pragma unroll
    for (int o = 16; o; o >>= 1) {
        sum += __shfl_xor_sync(0xffffffffu, sum, o);
        sq  += __shfl_xor_sync(0xffffffffu, sq, o);
    }
    float mu  = sum * (1.0f / DD);
    float var = sq * (1.0f / DD) - mu * mu;
    float inv = rsqrtf(var + 1e-6f);
#pragma unroll
    for (int i = 0; i < 24; i++) {
        int d = lane + i * 32;
        out[(size_t)row * DD + d] = gamma[d] * (v[i] - mu) * inv + beta[d];
    }
}

extern "C" void kernel_launch(void* const* d_in, const int* in_sizes, int n_in,
                              void* d_out, int out_size) {
    const int*   src        = (const int*)d_in[0];
    const int*   seg        = (const int*)d_in[1];
    const int*   type_ids   = (const int*)d_in[2];
    const int*   pos        = (const int*)d_in[3];
    const int*   span_start = (const int*)d_in[4];
    const int*   span_end   = (const int*)d_in[5];
    const int*   edge_idx   = (const int*)d_in[6];
    const float* word_table = (const float*)d_in[7];
    const float* pos_table  = (const float*)d_in[8];
    const float* seg_table  = (const float*)d_in[9];
    const float* type_table = (const float*)d_in[10];
    const float* gamma      = (const float*)d_in[11];
    const float* beta       = (const float*)d_in[12];
    const float* W_gat      = (const float*)d_in[13];
    const float* a_src      = (const float*)d_in[14];
    const float* a_dst      = (const float*)d_in[15];
    const float* b_gat      = (const float*)d_in[16];
    float* out = (float*)d_out;

    build_nodes<<<NN, 192>>>(src, span_start, span_end, word_table);

    for (int l = 0; l < 5; l++) {
        gemm_xw<<<dim3(12, 9), 256>>>(W_gat + (size_t)l * DD * DD);
        alphas_kernel<<<NN, 128>>>(a_src + l * HH * DHH, a_dst + l * HH * DHH);
        init_kernel<<<(NN * DD + 255) / 256, 256>>>();
        edge_logit<<<(NE * HH + 255) / 256, 256>>>(edge_idx);
        edge_exp<<<(NE * HH + 255) / 256, 256>>>(edge_idx);
        aggregate<<<(NE + 3) / 4, 128>>>(edge_idx);
        bias_gelu<<<(NN * DD + 255) / 256, 256>>>(b_gat + l * DD);
    }

    final_ln<<<(BB * SS) / 8, 256>>>(src, seg, type_ids, pos,
                                     word_table, pos_table, seg_table, type_table,
                                     gamma, beta, out);
}

// round 2
// speedup vs baseline: 2.8121x; 2.8121x over previous
#include <cuda_runtime.h>
#include <math.h>

#define BB 64
#define SS 512
#define DD 768
#define HH 4
#define DHH 192
#define PP 8
#define NPER 9
#define NN 576
#define E0 4096
#define NE 8768       // 2*E0 + NN self loops
#define KSPLIT 4
#define KCHUNK 192    // DD / KSPLIT

// ---------------- device scratch ----------------
__device__ float g_x[NN * DD];          // layer input / output
__device__ float g_h[NN * DD];          // h = x @ W (combined)
__device__ float g_hp[KSPLIT][NN * DD]; // split-K partials
__device__ float g_as[NN * HH];
__device__ float g_ad[NN * HH];
__device__ int   g_deg[NN];
__device__ int   g_off[NN + 1];
__device__ int   g_cur[NN];
__device__ int   g_srcv[NE];            // CSR src per dst-sorted edge

__device__ __forceinline__ void edge_sd(int e, const int* __restrict__ ei, int& s, int& d) {
    if (e < E0)          { s = ei[e];        d = ei[E0 + e]; }
    else if (e < 2 * E0) { s = ei[e];        d = ei[e - E0]; }   // ei[E0 + (e-E0)] = ei[e]
    else                 { s = e - 2 * E0;   d = e - 2 * E0; }
}

// ---------------- 1. node assembly ----------------
__global__ void build_nodes(const int* __restrict__ src,
                            const int* __restrict__ sstart,
                            const int* __restrict__ send,
                            const float* __restrict__ wt) {
    int node = blockIdx.x;
    int b = node / NPER, p = node % NPER;
    int t = threadIdx.x;               // 192
    int j0 = 4 * t;
    float4 v = make_float4(0.f, 0.f, 0.f, 0.f);
    if (p == 0) {
        v = *(const float4*)&wt[(size_t)src[b * SS] * DD + j0];
    } else {
        int st = sstart[b * PP + (p - 1)];
        int en = send[b * PP + (p - 1)];
        for (int s = st; s <= en; s++) {
            float4 w = *(const float4*)&wt[(size_t)src[b * SS + s] * DD + j0];
            v.x += w.x; v.y += w.y; v.z += w.z; v.w += w.w;
        }
    }
    *(float4*)&g_x[node * DD + j0] = v;
}

// ---------------- 2. CSR build ----------------
__global__ void zero_deg() {
    int t = threadIdx.x;
    if (t < NN) g_deg[t] = 0;
}
__global__ void csr_count(const int* __restrict__ ei) {
    int e = blockIdx.x * blockDim.x + threadIdx.x;
    if (e >= NE) return;
    int s, d; edge_sd(e, ei, s, d);
    atomicAdd(&g_deg[d], 1);
}
__global__ void csr_scan() {
    __shared__ int sh[1024];
    int t = threadIdx.x;
    int dv = (t < NN) ? g_deg[t] : 0;
    sh[t] = dv;
    __syncthreads();
    for (int off = 1; off < 1024; off <<= 1) {
        int v = (t >= off) ? sh[t - off] : 0;
        __syncthreads();
        sh[t] += v;
        __syncthreads();
    }
    if (t < NN) {
        g_off[t + 1] = sh[t];
        g_cur[t] = sh[t] - dv;
        if (t == 0) g_off[0] = 0;
    }
}
__global__ void csr_fill(const int* __restrict__ ei) {
    int e = blockIdx.x * blockDim.x + threadIdx.x;
    if (e >= NE) return;
    int s, d; edge_sd(e, ei, s, d);
    int pos = atomicAdd(&g_cur[d], 1);
    g_srcv[pos] = s;
}

// ---------------- 3. split-K GEMM: g_hp[z] = g_x @ W (partial) ----------------
__global__ void gemm_xw(const float* __restrict__ Wl) {
    __shared__ float As[16][68];
    __shared__ float Bs[16][64];
    int bm = blockIdx.y * 64, bn = blockIdx.x * 64;
    int kz = blockIdx.z * KCHUNK;
    int tid = threadIdx.x;
    int tr = tid >> 4, tc = tid & 15;
    float acc[4][4];
#pragma unroll
    for (int i = 0; i < 4; i++)
#pragma unroll
        for (int j = 0; j < 4; j++) acc[i][j] = 0.0f;

    for (int k0 = kz; k0 < kz + KCHUNK; k0 += 16) {
        for (int i = tid; i < 64 * 16; i += 256) {
            int m = i >> 4, k = i & 15;
            As[k][m] = g_x[(bm + m) * DD + k0 + k];
        }
        for (int i = tid; i < 16 * 64; i += 256) {
            int k = i >> 6, n = i & 63;
            Bs[k][n] = Wl[(size_t)(k0 + k) * DD + bn + n];
        }
        __syncthreads();
#pragma unroll
        for (int k = 0; k < 16; k++) {
            float4 a = *(const float4*)&As[k][tr * 4];
            float4 b = *(const float4*)&Bs[k][tc * 4];
            acc[0][0] += a.x * b.x; acc[0][1] += a.x * b.y; acc[0][2] += a.x * b.z; acc[0][3] += a.x * b.w;
            acc[1][0] += a.y * b.x; acc[1][1] += a.y * b.y; acc[1][2] += a.y * b.z; acc[1][3] += a.y * b.w;
            acc[2][0] += a.z * b.x; acc[2][1] += a.z * b.y; acc[2][2] += a.z * b.z; acc[2][3] += a.z * b.w;
            acc[3][0] += a.w * b.x; acc[3][1] += a.w * b.y; acc[3][2] += a.w * b.z; acc[3][3] += a.w * b.w;
        }
        __syncthreads();
    }
    float* dst = g_hp[blockIdx.z];
#pragma unroll
    for (int i = 0; i < 4; i++) {
        int gm = bm + tr * 4 + i;
        float4 o = make_float4(acc[i][0], acc[i][1], acc[i][2], acc[i][3]);
        *(float4*)&dst[gm * DD + bn + tc * 4] = o;
    }
}

// ---------------- 4. combine partials + alpha dots ----------------
__global__ void alphas_combine(const float* __restrict__ a_s,
                               const float* __restrict__ a_d) {
    __shared__ float ss[192], sd_[192];
    int node = blockIdx.x;
    int t = threadIdx.x;          // 192
    int j0 = 4 * t;
    int h = t / 48;
    size_t idx = (size_t)node * DD + j0;
    float4 v0 = *(const float4*)&g_hp[0][idx];
    float4 v1 = *(const float4*)&g_hp[1][idx];
    float4 v2 = *(const float4*)&g_hp[2][idx];
    float4 v3 = *(const float4*)&g_hp[3][idx];
    float4 v = make_float4(v0.x + v1.x + v2.x + v3.x,
                           v0.y + v1.y + v2.y + v3.y,
                           v0.z + v1.z + v2.z + v3.z,
                           v0.w + v1.w + v2.w + v3.w);
    *(float4*)&g_h[idx] = v;
    float4 as4 = *(const float4*)&a_s[j0];
    float4 ad4 = *(const float4*)&a_d[j0];
    float ds = v.x * as4.x + v.y * as4.y + v.z * as4.z + v.w * as4.w;
    float dd_ = v.x * ad4.x + v.y * ad4.y + v.z * ad4.z + v.w * ad4.w;
    ss[t] = ds; sd_[t] = dd_;
    __syncthreads();
    int tin = t - h * 48;
    for (int st = 24; st > 2; st >>= 1) {
        if (tin < st) { ss[t] += ss[t + st]; sd_[t] += sd_[t + st]; }
        __syncthreads();
    }
    if (tin == 0) {
        g_as[node * HH + h] = ss[t] + ss[t + 1] + ss[t + 2];
        g_ad[node * HH + h] = sd_[t] + sd_[t + 1] + sd_[t + 2];
    }
}

// ---------------- 5. per-dst softmax + aggregate + bias + GELU ----------------
__global__ void aggregate_gelu(const float* __restrict__ bias) {
    __shared__ float red[4][192];
    __shared__ float smax[4], sden[4];
    int d = blockIdx.x;
    int t = threadIdx.x;          // 192
    int beg = g_off[d], end = g_off[d + 1];
    float adh[4];
#pragma unroll
    for (int h = 0; h < 4; h++) adh[h] = g_ad[d * HH + h];

    // pass 1: per-head max of leaky-relu logits
    float mx[4] = {-3.0e38f, -3.0e38f, -3.0e38f, -3.0e38f};
    for (int e = beg + t; e < end; e += 192) {
        int s = g_srcv[e];
#pragma unroll
        for (int h = 0; h < 4; h++) {
            float l = g_as[s * HH + h] + adh[h];
            l = (l > 0.0f) ? l : 0.2f * l;
            mx[h] = fmaxf(mx[h], l);
        }
    }
#pragma unroll
    for (int h = 0; h < 4; h++) red[h][t] = mx[h];
    __syncthreads();
    for (int st = 96; st > 2; st >>= 1) {
        if (t < st)
#pragma unroll
            for (int h = 0; h < 4; h++) red[h][t] = fmaxf(red[h][t], red[h][t + st]);
        __syncthreads();
    }
    if (t < 4) smax[t] = fmaxf(fmaxf(red[t][0], red[t][1]), red[t][2]);
    __syncthreads();

    // pass 2: per-head sum of exp
    float sm[4] = {0.f, 0.f, 0.f, 0.f};
    float m0 = smax[0], m1 = smax[1], m2 = smax[2], m3 = smax[3];
    for (int e = beg + t; e < end; e += 192) {
        int s = g_srcv[e];
        float l0 = g_as[s * HH + 0] + adh[0]; l0 = (l0 > 0.f) ? l0 : 0.2f * l0;
        float l1 = g_as[s * HH + 1] + adh[1]; l1 = (l1 > 0.f) ? l1 : 0.2f * l1;
        float l2 = g_as[s * HH + 2] + adh[2]; l2 = (l2 > 0.f) ? l2 : 0.2f * l2;
        float l3 = g_as[s * HH + 3] + adh[3]; l3 = (l3 > 0.f) ? l3 : 0.2f * l3;
        sm[0] += expf(l0 - m0); sm[1] += expf(l1 - m1);
        sm[2] += expf(l2 - m2); sm[3] += expf(l3 - m3);
    }
    __syncthreads();
#pragma unroll
    for (int h = 0; h < 4; h++) red[h][t] = sm[h];
    __syncthreads();
    for (int st = 96; st > 2; st >>= 1) {
        if (t < st)
#pragma unroll
            for (int h = 0; h < 4; h++) red[h][t] += red[h][t + st];
        __syncthreads();
    }
    if (t < 4) sden[t] = red[t][0] + red[t][1] + red[t][2];
    __syncthreads();

    // pass 3: weighted gather, bias, GELU
    int j0 = 4 * t;
    int h = t / 48;
    float m_ = smax[h];
    float inv = 1.0f / sden[h];
    float ah = adh[h];
    float4 acc = make_float4(0.f, 0.f, 0.f, 0.f);
    for (int e = beg; e < end; e++) {
        int s = g_srcv[e];
        float l = g_as[s * HH + h] + ah;
        l = (l > 0.0f) ? l : 0.2f * l;
        float att = expf(l - m_) * inv;
        float4 hv = *(const float4*)&g_h[(size_t)s * DD + j0];
        acc.x += att * hv.x; acc.y += att * hv.y;
        acc.z += att * hv.z; acc.w += att * hv.w;
    }
    float4 b4 = *(const float4*)&bias[j0];
    float o[4] = {acc.x + b4.x, acc.y + b4.y, acc.z + b4.z, acc.w + b4.w};
    float4 r;
    r.x = 0.5f * o[0] * (1.0f + erff(o[0] * 0.70710678118654752f));
    r.y = 0.5f * o[1] * (1.0f + erff(o[1] * 0.70710678118654752f));
    r.z = 0.5f * o[2] * (1.0f + erff(o[2] * 0.70710678118654752f));
    r.w = 0.5f * o[3] * (1.0f + erff(o[3] * 0.70710678118654752f));
    *(float4*)&g_x[(size_t)d * DD + j0] = r;
}

// ---------------- 6. final embedding sum + LayerNorm ----------------
__global__ void final_ln(const int* __restrict__ src, const int* __restrict__ seg,
                         const int* __restrict__ typ, const int* __restrict__ pos,
                         const float* __restrict__ wt, const float* __restrict__ pt,
                         const float* __restrict__ st, const float* __restrict__ tt,
                         const float* __restrict__ gamma, const float* __restrict__ beta,
                         float* __restrict__ out) {
    int row = blockIdx.x * 8 + (threadIdx.x >> 5);
    int lane = threadIdx.x & 31;
    int b = row / SS, s = row % SS;
    const float* wrow = (s == 0) ? &g_x[(size_t)(b * NPER) * DD]
                                 : &wt[(size_t)src[row] * DD];
    const float* prow = &pt[(size_t)pos[row] * DD];
    const float* srow = &st[(size_t)seg[row] * DD];
    const float* trow = &tt[(size_t)typ[row] * DD];
    float4 v[6];
    float sum = 0.0f, sq = 0.0f;
#pragma unroll
    for (int i = 0; i < 6; i++) {
        int f = (lane + i * 32) * 4;
        float4 w = *(const float4*)&wrow[f];
        float4 p = *(const float4*)&prow[f];
        float4 sg = *(const float4*)&srow[f];
        float4 ty = *(const float4*)&trow[f];
        float4 e = make_float4(w.x + p.x + sg.x + ty.x, w.y + p.y + sg.y + ty.y,
                               w.z + p.z + sg.z + ty.z, w.w + p.w + sg.w + ty.w);
        v[i] = e;
        sum += e.x + e.y + e.z + e.w;
        sq += e.x * e.x + e.y * e.y + e.z * e.z + e.w * e.w;
    }
#pragma unroll
    for (int o = 16; o; o >>= 1) {
        sum += __shfl_xor_sync(0xffffffffu, sum, o);
        sq  += __shfl_xor_sync(0xffffffffu, sq, o);
    }
    float mu  = sum * (1.0f / DD);
    float var = sq * (1.0f / DD) - mu * mu;
    float inv = rsqrtf(var + 1e-6f);
#pragma unroll
    for (int i = 0; i < 6; i++) {
        int f = (lane + i * 32) * 4;
        float4 g4 = *(const float4*)&gamma[f];
        float4 b4 = *(const float4*)&beta[f];
        float4 r;
        r.x = g4.x * (v[i].x - mu) * inv + b4.x;
        r.y = g4.y * (v[i].y - mu) * inv + b4.y;
        r.z = g4.z * (v[i].z - mu) * inv + b4.z;
        r.w = g4.w * (v[i].w - mu) * inv + b4.w;
        *(float4*)&out[(size_t)row * DD + f] = r;
    }
}

extern "C" void kernel_launch(void* const* d_in, const int* in_sizes, int n_in,
                              void* d_out, int out_size) {
    const int*   src        = (const int*)d_in[0];
    const int*   seg        = (const int*)d_in[1];
    const int*   type_ids   = (const int*)d_in[2];
    const int*   pos        = (const int*)d_in[3];
    const int*   span_start = (const int*)d_in[4];
    const int*   span_end   = (const int*)d_in[5];
    const int*   edge_idx   = (const int*)d_in[6];
    const float* word_table = (const float*)d_in[7];
    const float* pos_table  = (const float*)d_in[8];
    const float* seg_table  = (const float*)d_in[9];
    const float* type_table = (const float*)d_in[10];
    const float* gamma      = (const float*)d_in[11];
    const float* beta       = (const float*)d_in[12];
    const float* W_gat      = (const float*)d_in[13];
    const float* a_src      = (const float*)d_in[14];
    const float* a_dst      = (const float*)d_in[15];
    const float* b_gat      = (const float*)d_in[16];
    float* out = (float*)d_out;

    build_nodes<<<NN, 192>>>(src, span_start, span_end, word_table);
    zero_deg<<<1, 576>>>();
    csr_count<<<(NE + 255) / 256, 256>>>(edge_idx);
    csr_scan<<<1, 1024>>>();
    csr_fill<<<(NE + 255) / 256, 256>>>(edge_idx);

    for (int l = 0; l < 5; l++) {
        gemm_xw<<<dim3(12, 9, KSPLIT), 256>>>(W_gat + (size_t)l * DD * DD);
        alphas_combine<<<NN, 192>>>(a_src + l * DD, a_dst + l * DD);
        aggregate_gelu<<<NN, 192>>>(b_gat + l * DD);
    }

    final_ln<<<(BB * SS) / 8, 256>>>(src, seg, type_ids, pos,
                                     word_table, pos_table, seg_table, type_table,
                                     gamma, beta, out);
}

// round 7
// speedup vs baseline: 4.2669x; 1.5173x over previous
#include <cuda_runtime.h>
#include <math.h>
#include <stdint.h>

#define BB 64
#define SS 512
#define DD 768
#define HH 4
#define DHH 192
#define PP 8
#define NPER 9
#define NN 576
#define E0 4096
#define NE 8768       // 2*E0 + NN self loops
#define KTILES 24     // 768 / 32
#define AP 36
#define BP 72

// ---------------- device scratch ----------------
__device__ float g_x[NN * DD];
__device__ float g_h[NN * DD];
__device__ float g_as[NN * HH];
__device__ float g_ad[NN * HH];
__device__ float g_was[5 * 8 * DD];     // per layer: slots 0-3 = W@a_src heads, 4-7 = W@a_dst
__device__ int   g_deg[NN];
__device__ int   g_off[NN + 1];
__device__ int   g_cur[NN];
__device__ int   g_srcv[NE];

__device__ __forceinline__ void edge_sd(int e, const int* __restrict__ ei, int& s, int& d) {
    if (e < E0)          { s = ei[e];      d = ei[E0 + e]; }
    else if (e < 2 * E0) { s = ei[e];      d = ei[e - E0]; }
    else                 { s = e - 2 * E0; d = e - 2 * E0; }
}

__device__ __forceinline__ void cpa16(uint32_t saddr, const void* gptr) {
    asm volatile("cp.async.cg.shared.global [%0], [%1], 16;\n" :: "r"(saddr), "l"(gptr));
}
__device__ __forceinline__ void cpa_commit() { asm volatile("cp.async.commit_group;\n"); }

// ---------------- 1. node assembly (+deg zero) ----------------
__global__ void build_nodes(const int* __restrict__ src,
                            const int* __restrict__ sstart,
                            const int* __restrict__ send,
                            const float* __restrict__ wt) {
    int node = blockIdx.x;
    if (threadIdx.x == 0) g_deg[node] = 0;
    int b = node / NPER, p = node % NPER;
    int j0 = 4 * threadIdx.x;
    float4 v = make_float4(0.f, 0.f, 0.f, 0.f);
    if (p == 0) {
        v = *(const float4*)&wt[(size_t)src[b * SS] * DD + j0];
    } else {
        int st = sstart[b * PP + (p - 1)];
        int en = send[b * PP + (p - 1)];
        for (int s = st; s <= en; s++) {
            float4 w = *(const float4*)&wt[(size_t)src[b * SS + s] * DD + j0];
            v.x += w.x; v.y += w.y; v.z += w.z; v.w += w.w;
        }
    }
    *(float4*)&g_x[node * DD + j0] = v;
}

// ---------------- 2. CSR build ----------------
__global__ void csr_count(const int* __restrict__ ei) {
    int e = blockIdx.x * blockDim.x + threadIdx.x;
    if (e >= NE) return;
    int s, d; edge_sd(e, ei, s, d);
    atomicAdd(&g_deg[d], 1);
}
__global__ void csr_scan() {
    __shared__ int sh[1024];
    int t = threadIdx.x;
    int dv = (t < NN) ? g_deg[t] : 0;
    sh[t] = dv;
    __syncthreads();
    for (int off = 1; off < 1024; off <<= 1) {
        int v = (t >= off) ? sh[t - off] : 0;
        __syncthreads();
        sh[t] += v;
        __syncthreads();
    }
    if (t < NN) {
        g_off[t + 1] = sh[t];
        g_cur[t] = sh[t] - dv;
        if (t == 0) g_off[0] = 0;
    }
}
__global__ void csr_fill(const int* __restrict__ ei) {
    int e = blockIdx.x * blockDim.x + threadIdx.x;
    if (e >= NE) return;
    int s, d; edge_sd(e, ei, s, d);
    int pos = atomicAdd(&g_cur[d], 1);
    g_srcv[pos] = s;
}

// ---------------- 3. precompute w_as = W @ a_src / a_dst (all 5 layers) ----------------
__global__ void prep_was(const float* __restrict__ W,
                         const float* __restrict__ a_s,
                         const float* __restrict__ a_d) {
    int l = blockIdx.x / 12;
    int kt = blockIdx.x % 12;
    int t = threadIdx.x;
    int k = kt * 64 + (t & 63);
    int sp = t >> 6;                      // head 0..3
    const float* wseg = W + (size_t)l * DD * DD + (size_t)k * DD + sp * DHH;
    const float* av = a_s + l * DD + sp * DHH;
    const float* bv = a_d + l * DD + sp * DHH;
    float s0 = 0.f, s1 = 0.f;
#pragma unroll 8
    for (int i = 0; i < DHH; i += 4) {
        float4 w = *(const float4*)&wseg[i];
        float4 a = *(const float4*)&av[i];
        float4 b = *(const float4*)&bv[i];
        s0 += w.x * a.x + w.y * a.y + w.z * a.z + w.w * a.w;
        s1 += w.x * b.x + w.y * b.y + w.z * b.z + w.w * b.w;
    }
    g_was[(l * 8 + sp) * DD + k]     = s0;
    g_was[(l * 8 + sp + 4) * DD + k] = s1;
}

// ---------------- 4. tf32 tensor-core GEMM g_h = g_x @ W, alpha sidecar on bn==0 ----------------
__global__ __launch_bounds__(256) void gemm_xw(const float* __restrict__ Wl,
                                               const float* __restrict__ wasl) {
    __shared__ __align__(16) float As[2][64][AP];
    __shared__ __align__(16) float Bs[2][32][BP];
    __shared__ __align__(16) float Ws[2][8][32];
    int tid = threadIdx.x;
    int bm = blockIdx.y * 64, bn = blockIdx.x * 64;
    bool side = (blockIdx.x == 0);
    int wid = tid >> 5, lane = tid & 31;
    int wm = wid >> 2, wn = wid & 3;
    int g = lane >> 2, tig = lane & 3;

    float d[2][2][4];
#pragma unroll
    for (int i = 0; i < 2; i++)
#pragma unroll
        for (int j = 0; j < 2; j++)
#pragma unroll
            for (int q = 0; q < 4; q++) d[i][j][q] = 0.f;

    float sa0 = 0.f, sa1 = 0.f;
    int sr = tid & 63, sp = tid >> 6;

    // g2s assignments
    int am1 = tid >> 3, aq = tid & 7;            // A: m, float4-col (items tid, tid+256)
    int bk1 = tid >> 4, bq = tid & 15;           // B: k, float4-col
    int wslot = tid >> 3, wq = tid & 7;          // Ws: tid<64

    uint32_t as_base = (uint32_t)__cvta_generic_to_shared(&As[0][0][0]);
    uint32_t bs_base = (uint32_t)__cvta_generic_to_shared(&Bs[0][0][0]);
    uint32_t ws_base = (uint32_t)__cvta_generic_to_shared(&Ws[0][0][0]);

#define LOAD_TILE(buf, k0)                                                              \
    do {                                                                                \
        cpa16(as_base + ((buf) * 64 * AP + am1 * AP + aq * 4) * 4,                      \
              &g_x[(bm + am1) * DD + (k0) + aq * 4]);                                   \
        cpa16(as_base + ((buf) * 64 * AP + (am1 + 32) * AP + aq * 4) * 4,               \
              &g_x[(bm + am1 + 32) * DD + (k0) + aq * 4]);                              \
        cpa16(bs_base + ((buf) * 32 * BP + bk1 * BP + bq * 4) * 4,                      \
              &Wl[(size_t)((k0) + bk1) * DD + bn + bq * 4]);                            \
        cpa16(bs_base + ((buf) * 32 * BP + (bk1 + 16) * BP + bq * 4) * 4,               \
              &Wl[(size_t)((k0) + bk1 + 16) * DD + bn + bq * 4]);                       \
        if (side && tid < 64)                                                           \
            cpa16(ws_base + ((buf) * 8 * 32 + wslot * 32 + wq * 4) * 4,                 \
                  &wasl[wslot * DD + (k0) + wq * 4]);                                   \
        cpa_commit();                                                                   \
    } while (0)

    LOAD_TILE(0, 0);

#pragma unroll 1
    for (int t = 0; t < KTILES; t++) {
        if (t + 1 < KTILES) {
            LOAD_TILE((t + 1) & 1, (t + 1) * 32);
            asm volatile("cp.async.wait_group 1;\n");
        } else {
            asm volatile("cp.async.wait_group 0;\n");
        }
        __syncthreads();
        int buf = t & 1;
#pragma unroll
        for (int ks = 0; ks < 4; ks++) {
            int kk = ks * 8;
            uint32_t a[2][4], b[2][2];
#pragma unroll
            for (int mt = 0; mt < 2; mt++) {
                int r0 = wm * 32 + mt * 16 + g;
                a[mt][0] = __float_as_uint(As[buf][r0][kk + tig]);
                a[mt][1] = __float_as_uint(As[buf][r0 + 8][kk + tig]);
                a[mt][2] = __float_as_uint(As[buf][r0][kk + tig + 4]);
                a[mt][3] = __float_as_uint(As[buf][r0 + 8][kk + tig + 4]);
            }
#pragma unroll
            for (int nt = 0; nt < 2; nt++) {
                int c0 = wn * 16 + nt * 8 + g;
                b[nt][0] = __float_as_uint(Bs[buf][kk + tig][c0]);
                b[nt][1] = __float_as_uint(Bs[buf][kk + tig + 4][c0]);
            }
#pragma unroll
            for (int mt = 0; mt < 2; mt++)
#pragma unroll
                for (int nt = 0; nt < 2; nt++) {
                    asm volatile(
                        "mma.sync.aligned.m16n8k8.row.col.f32.tf32.tf32.f32 "
                        "{%0,%1,%2,%3}, {%4,%5,%6,%7}, {%8,%9}, {%0,%1,%2,%3};\n"
                        : "+f"(d[mt][nt][0]), "+f"(d[mt][nt][1]),
                          "+f"(d[mt][nt][2]), "+f"(d[mt][nt][3])
                        : "r"(a[mt][0]), "r"(a[mt][1]), "r"(a[mt][2]), "r"(a[mt][3]),
                          "r"(b[nt][0]), "r"(b[nt][1]));
                }
        }
        if (side) {
#pragma unroll
            for (int q = 0; q < 8; q++) {
                float4 xv = *(const float4*)&As[buf][sr][q * 4];
                float4 w0 = *(const float4*)&Ws[buf][sp][q * 4];
                float4 w1 = *(const float4*)&Ws[buf][sp + 4][q * 4];
                sa0 += xv.x * w0.x + xv.y * w0.y + xv.z * w0.z + xv.w * w0.w;
                sa1 += xv.x * w1.x + xv.y * w1.y + xv.z * w1.z + xv.w * w1.w;
            }
        }
        __syncthreads();
    }

#pragma unroll
    for (int mt = 0; mt < 2; mt++)
#pragma unroll
        for (int nt = 0; nt < 2; nt++) {
            int row = bm + wm * 32 + mt * 16 + g;
            int col = bn + wn * 16 + nt * 8 + 2 * tig;
            *(float2*)&g_h[(size_t)row * DD + col] =
                make_float2(d[mt][nt][0], d[mt][nt][1]);
            *(float2*)&g_h[(size_t)(row + 8) * DD + col] =
                make_float2(d[mt][nt][2], d[mt][nt][3]);
        }
    if (side) {
        int r = bm + sr;
        g_as[r * HH + sp] = sa0;
        g_ad[r * HH + sp] = sa1;
    }
#undef LOAD_TILE
}

// ---------------- 5. per-dst softmax + aggregate + bias + GELU ----------------
__global__ void aggregate_gelu(const float* __restrict__ bias) {
    __shared__ float red[4][192];
    __shared__ float smax[4], sden[4];
    int d = blockIdx.x;
    int t = threadIdx.x;          // 192
    int beg = g_off[d], end = g_off[d + 1];
    float adh[4];
#pragma unroll
    for (int h = 0; h < 4; h++) adh[h] = g_ad[d * HH + h];

    float mx[4] = {-3.0e38f, -3.0e38f, -3.0e38f, -3.0e38f};
    for (int e = beg + t; e < end; e += 192) {
        int s = g_srcv[e];
#pragma unroll
        for (int h = 0; h < 4; h++) {
            float l = g_as[s * HH + h] + adh[h];
            l = (l > 0.0f) ? l : 0.2f * l;
            mx[h] = fmaxf(mx[h], l);
        }
    }
#pragma unroll
    for (int h = 0; h < 4; h++) red[h][t] = mx[h];
    __syncthreads();
    for (int st = 96; st > 2; st >>= 1) {
        if (t < st)
#pragma unroll
            for (int h = 0; h < 4; h++) red[h][t] = fmaxf(red[h][t], red[h][t + st]);
        __syncthreads();
    }
    if (t < 4) smax[t] = fmaxf(fmaxf(red[t][0], red[t][1]), red[t][2]);
    __syncthreads();

    float sm[4] = {0.f, 0.f, 0.f, 0.f};
    float m0 = smax[0], m1 = smax[1], m2 = smax[2], m3 = smax[3];
    for (int e = beg + t; e < end; e += 192) {
        int s = g_srcv[e];
        float l0 = g_as[s * HH + 0] + adh[0]; l0 = (l0 > 0.f) ? l0 : 0.2f * l0;
        float l1 = g_as[s * HH + 1] + adh[1]; l1 = (l1 > 0.f) ? l1 : 0.2f * l1;
        float l2 = g_as[s * HH + 2] + adh[2]; l2 = (l2 > 0.f) ? l2 : 0.2f * l2;
        float l3 = g_as[s * HH + 3] + adh[3]; l3 = (l3 > 0.f) ? l3 : 0.2f * l3;
        sm[0] += expf(l0 - m0); sm[1] += expf(l1 - m1);
        sm[2] += expf(l2 - m2); sm[3] += expf(l3 - m3);
    }
    __syncthreads();
#pragma unroll
    for (int h = 0; h < 4; h++) red[h][t] = sm[h];
    __syncthreads();
    for (int st = 96; st > 2; st >>= 1) {
        if (t < st)
#pragma unroll
            for (int h = 0; h < 4; h++) red[h][t] += red[h][t + st];
        __syncthreads();
    }
    if (t < 4) sden[t] = red[t][0] + red[t][1] + red[t][2];
    __syncthreads();

    int j0 = 4 * t;
    int h = t / 48;
    float m_ = smax[h];
    float inv = 1.0f / sden[h];
    float ah = adh[h];
    float4 acc = make_float4(0.f, 0.f, 0.f, 0.f);
    for (int e = beg; e < end; e++) {
        int s = g_srcv[e];
        float l = g_as[s * HH + h] + ah;
        l = (l > 0.0f) ? l : 0.2f * l;
        float att = expf(l - m_) * inv;
        float4 hv = *(const float4*)&g_h[(size_t)s * DD + j0];
        acc.x += att * hv.x; acc.y += att * hv.y;
        acc.z += att * hv.z; acc.w += att * hv.w;
    }
    float4 b4 = *(const float4*)&bias[j0];
    float o[4] = {acc.x + b4.x, acc.y + b4.y, acc.z + b4.z, acc.w + b4.w};
    float4 r;
    r.x = 0.5f * o[0] * (1.0f + erff(o[0] * 0.70710678118654752f));
    r.y = 0.5f * o[1] * (1.0f + erff(o[1] * 0.70710678118654752f));
    r.z = 0.5f * o[2] * (1.0f + erff(o[2] * 0.70710678118654752f));
    r.w = 0.5f * o[3] * (1.0f + erff(o[3] * 0.70710678118654752f));
    *(float4*)&g_x[(size_t)d * DD + j0] = r;
}

// ---------------- 6. final embedding sum + LayerNorm ----------------
__global__ void final_ln(const int* __restrict__ src, const int* __restrict__ seg,
                         const int* __restrict__ typ, const int* __restrict__ pos,
                         const float* __restrict__ wt, const float* __restrict__ pt,
                         const float* __restrict__ st, const float* __restrict__ tt,
                         const float* __restrict__ gamma, const float* __restrict__ beta,
                         float* __restrict__ out) {
    int row = blockIdx.x * 8 + (threadIdx.x >> 5);
    int lane = threadIdx.x & 31;
    int b = row / SS, s = row % SS;
    const float* wrow = (s == 0) ? &g_x[(size_t)(b * NPER) * DD]
                                 : &wt[(size_t)src[row] * DD];
    const float* prow = &pt[(size_t)pos[row] * DD];
    const float* srow = &st[(size_t)seg[row] * DD];
    const float* trow = &tt[(size_t)typ[row] * DD];
    float4 v[6];
    float sum = 0.0f, sq = 0.0f;
#pragma unroll
    for (int i = 0; i < 6; i++) {
        int f = (lane + i * 32) * 4;
        float4 w = *(const float4*)&wrow[f];
        float4 p = *(const float4*)&prow[f];
        float4 sg = *(const float4*)&srow[f];
        float4 ty = *(const float4*)&trow[f];
        float4 e = make_float4(w.x + p.x + sg.x + ty.x, w.y + p.y + sg.y + ty.y,
                               w.z + p.z + sg.z + ty.z, w.w + p.w + sg.w + ty.w);
        v[i] = e;
        sum += e.x + e.y + e.z + e.w;
        sq += e.x * e.x + e.y * e.y + e.z * e.z + e.w * e.w;
    }
#pragma unroll
    for (int o = 16; o; o >>= 1) {
        sum += __shfl_xor_sync(0xffffffffu, sum, o);
        sq  += __shfl_xor_sync(0xffffffffu, sq, o);
    }
    float mu  = sum * (1.0f / DD);
    float var = sq * (1.0f / DD) - mu * mu;
    float inv = rsqrtf(var + 1e-6f);
#pragma unroll
    for (int i = 0; i < 6; i++) {
        int f = (lane + i * 32) * 4;
        float4 g4 = *(const float4*)&gamma[f];
        float4 b4 = *(const float4*)&beta[f];
        float4 r;
        r.x = g4.x * (v[i].x - mu) * inv + b4.x;
        r.y = g4.y * (v[i].y - mu) * inv + b4.y;
        r.z = g4.z * (v[i].z - mu) * inv + b4.z;
        r.w = g4.w * (v[i].w - mu) * inv + b4.w;
        *(float4*)&out[(size_t)row * DD + f] = r;
    }
}

extern "C" void kernel_launch(void* const* d_in, const int* in_sizes, int n_in,
                              void* d_out, int out_size) {
    const int*   src        = (const int*)d_in[0];
    const int*   seg        = (const int*)d_in[1];
    const int*   type_ids   = (const int*)d_in[2];
    const int*   pos        = (const int*)d_in[3];
    const int*   span_start = (const int*)d_in[4];
    const int*   span_end   = (const int*)d_in[5];
    const int*   edge_idx   = (const int*)d_in[6];
    const float* word_table = (const float*)d_in[7];
    const float* pos_table  = (const float*)d_in[8];
    const float* seg_table  = (const float*)d_in[9];
    const float* type_table = (const float*)d_in[10];
    const float* gamma      = (const float*)d_in[11];
    const float* beta       = (const float*)d_in[12];
    const float* W_gat      = (const float*)d_in[13];
    const float* a_src      = (const float*)d_in[14];
    const float* a_dst      = (const float*)d_in[15];
    const float* b_gat      = (const float*)d_in[16];
    float* out = (float*)d_out;

    build_nodes<<<NN, 192>>>(src, span_start, span_end, word_table);
    csr_count<<<(NE + 255) / 256, 256>>>(edge_idx);
    csr_scan<<<1, 1024>>>();
    csr_fill<<<(NE + 255) / 256, 256>>>(edge_idx);
    prep_was<<<60, 256>>>(W_gat, a_src, a_dst);

    float* was_dev;
    cudaGetSymbolAddress((void**)&was_dev, g_was);

    for (int l = 0; l < 5; l++) {
        gemm_xw<<<dim3(12, 9), 256>>>(W_gat + (size_t)l * DD * DD,
                                      was_dev + (size_t)l * 8 * DD);
        aggregate_gelu<<<NN, 192>>>(b_gat + l * DD);
    }

    final_ln<<<(BB * SS) / 8, 256>>>(src, seg, type_ids, pos,
                                     word_table, pos_table, seg_table, type_table,
                                     gamma, beta, out);
}